// round 11
// baseline (speedup 1.0000x reference)
#include <cuda_runtime.h>
#include <cuda_fp16.h>
#include <cstdint>

#define N_NODES 200000
#define DIM     64
#define NNZ_E   6400000
#define NE      (N_NODES * DIM)

#define NBUCK        196          // ceil(200000 / 1024)
#define BUCK_CAP     36864        // mean 32768, sd ~181 -> +22 sigma margin
#define TILE_E       2048         // edges per phase-1 block (3125 blocks exact)

// Scratch: __device__ globals (allocation-free rule). ~212 MB.
// g_gcur is zero at module load and re-zeroed by the last layer kernel of every
// execution, so each run (correctness pass + every replay) starts clean.
__device__ __half g_h[NE];                        // 25.6 MB
__device__ __half g_m1[NE];                       // 25.6 MB
__device__ __half g_m2[NE];                       // 25.6 MB
__device__ __half g_m3[NE];                       // 25.6 MB
__device__ int2   g_cv[NNZ_E];                    // 51.2 MB (col, val-bits) CSR
__device__ int2   g_stage[NBUCK * BUCK_CAP];      // 57.8 MB bucketed staging
__device__ int    g_gcur[NBUCK];                  // per-bucket cursors/counts
__device__ int    g_rowptr[N_NODES + 1];

// ---------------------------------------------------------------------------
// Launch 0: logmap0 (c=1) -> fp16 h.  one warp per row, lane owns {2l,2l+1}
// ---------------------------------------------------------------------------
__global__ void logmap_kernel(const float* __restrict__ x, __half2* __restrict__ h) {
    int row  = blockIdx.x * (blockDim.x >> 5) + (threadIdx.x >> 5);
    int lane = threadIdx.x & 31;
    if (row >= N_NODES) return;

    float2 v = reinterpret_cast<const float2*>(x + (size_t)row * DIM)[lane];
    float x0 = __shfl_sync(0xFFFFFFFFu, v.x, 0);
    float ss = v.y * v.y + (lane ? v.x * v.x : 0.0f);
    #pragma unroll
    for (int o = 16; o; o >>= 1) ss += __shfl_xor_sync(0xFFFFFFFFu, ss, o);

    float y_norm = fmaxf(sqrtf(ss), 1e-15f);
    float theta  = fmaxf(x0, 1.0f + 1e-7f);
    float s      = acoshf(theta) / y_norm;

    float2 o2;
    o2.x = lane ? s * v.x : 0.0f;
    o2.y = s * v.y;
    h[(size_t)row * 32 + lane] = __float22half2_rn(o2);
}

// ---------------------------------------------------------------------------
// Launch 1 (phase 1): bucket-binning of edges.
// Each block handles TILE_E edges: SMEM per-bucket counts -> ONE global atomic
// per (tile, bucket) to reserve staging space -> direct packed writes.
// Packed: .x = (row_local<<18) | col   (row_local<1024, col<262144), .y = val
// ---------------------------------------------------------------------------
__global__ void __launch_bounds__(256)
phase1_bin_kernel(const int* __restrict__ rows, const int* __restrict__ cols,
                  const float* __restrict__ vals,
                  int* __restrict__ gcur, int2* __restrict__ stage) {
    __shared__ int cnt[NBUCK];
    __shared__ int base[NBUCK];
    __shared__ int cur[NBUCK];
    int tid = threadIdx.x;
    long long e0 = (long long)blockIdx.x * TILE_E + (long long)tid * 8;

    if (tid < NBUCK) cnt[tid] = 0;
    __syncthreads();

    // 8 contiguous edges per thread, vectorized loads
    int4   ra = __ldg((const int4*)(rows + e0));
    int4   rb = __ldg((const int4*)(rows + e0 + 4));
    int4   ca = __ldg((const int4*)(cols + e0));
    int4   cb = __ldg((const int4*)(cols + e0 + 4));
    float4 va = __ldg((const float4*)(vals + e0));
    float4 vb = __ldg((const float4*)(vals + e0 + 4));

    int   r[8] = {ra.x, ra.y, ra.z, ra.w, rb.x, rb.y, rb.z, rb.w};
    int   c[8] = {ca.x, ca.y, ca.z, ca.w, cb.x, cb.y, cb.z, cb.w};
    float v[8] = {va.x, va.y, va.z, va.w, vb.x, vb.y, vb.z, vb.w};

    #pragma unroll
    for (int k = 0; k < 8; ++k) atomicAdd(&cnt[r[k] >> 10], 1);
    __syncthreads();

    if (tid < NBUCK) {
        int n = cnt[tid];
        base[tid] = n ? atomicAdd(&gcur[tid], n) : 0;
        cur[tid]  = 0;
    }
    __syncthreads();

    #pragma unroll
    for (int k = 0; k < 8; ++k) {
        int b = r[k] >> 10;
        int s = atomicAdd(&cur[b], 1);
        stage[(size_t)b * BUCK_CAP + base[b] + s] =
            make_int2(((r[k] & 1023) << 18) | c[k], __float_as_int(v[k]));
    }
}

// ---------------------------------------------------------------------------
// Launch 2 (phase 2): per-bucket CSR build. One 1024-thread block per bucket.
// All per-edge atomics are SMEM atomics; rowptr written coalesced.
// ---------------------------------------------------------------------------
__global__ void __launch_bounds__(1024)
phase2_csr_kernel(const int* __restrict__ gcur, const int2* __restrict__ stage,
                  int2* __restrict__ cv, int* __restrict__ rowptr) {
    __shared__ int pre[NBUCK];    // exclusive prefix of bucket counts
    __shared__ int cnt[1024];
    __shared__ int cur[1024];
    __shared__ int wsum[32];

    int b = blockIdx.x, tid = threadIdx.x;
    int lane = tid & 31, wid = tid >> 5;

    if (tid < NBUCK) pre[tid] = gcur[tid];
    __syncthreads();
    if (tid < 32) {                       // single-warp exclusive scan of 196
        int carry = 0;
        for (int b0 = 0; b0 < NBUCK; b0 += 32) {
            int i = b0 + lane;
            int val = (i < NBUCK) ? pre[i] : 0;
            int x = val;
            #pragma unroll
            for (int o = 1; o < 32; o <<= 1) {
                int y = __shfl_up_sync(0xFFFFFFFFu, x, o);
                if (lane >= o) x += y;
            }
            if (i < NBUCK) pre[i] = carry + x - val;
            carry += __shfl_sync(0xFFFFFFFFu, x, 31);
        }
    }
    cnt[tid] = 0;
    __syncthreads();

    int bucket_base = pre[b];
    int n = gcur[b];
    const int2* sb = stage + (size_t)b * BUCK_CAP;

    // pass 1: per-row counts (SMEM atomics)
    for (int j = tid; j < n; j += 1024)
        atomicAdd(&cnt[sb[j].x >> 18], 1);
    __syncthreads();

    // block exclusive scan of 1024 row counts
    int v = cnt[tid];
    int x = v;
    #pragma unroll
    for (int o = 1; o < 32; o <<= 1) {
        int y = __shfl_up_sync(0xFFFFFFFFu, x, o);
        if (lane >= o) x += y;
    }
    if (lane == 31) wsum[wid] = x;
    __syncthreads();
    if (tid < 32) {
        int s = wsum[lane];
        #pragma unroll
        for (int o = 1; o < 32; o <<= 1) {
            int y = __shfl_up_sync(0xFFFFFFFFu, s, o);
            if (lane >= o) s += y;
        }
        wsum[lane] = s;
    }
    __syncthreads();
    int excl  = (x - v) + (wid ? wsum[wid - 1] : 0);
    int gbase = bucket_base + excl;

    cur[tid] = gbase;
    int row = b * 1024 + tid;
    if (row <= N_NODES) rowptr[row] = gbase;   // includes the NNZ sentinel
    __syncthreads();

    // pass 2: scatter into CSR order (SMEM cursor atomics)
    for (int j = tid; j < n; j += 1024) {
        int2 w   = sb[j];
        int  rl  = w.x >> 18;
        int  pos = atomicAdd(&cur[rl], 1);
        cv[pos]  = make_int2(w.x & 0x3FFFF, w.y);
    }
}

// ---------------------------------------------------------------------------
// Launches 3-6: CSR SpMM  dst = A * src  (fp16 .cg gather, fp32 accumulate)
// Pairwise gather: lanes 0-15 edge e, lanes 16-31 edge e+1; 8 B per lane.
// 16 edges/iter main loop.  Last layer fuses out = 4*m1+5*m2+3*m3+A*m3 and
// re-zeroes the phase-1 bucket cursors for the next execution.
// ---------------------------------------------------------------------------
__global__ void __launch_bounds__(256)
csr_spmm_kernel(const int* __restrict__ rowptr, const int2* __restrict__ cv,
                const uint2* __restrict__ src, uint2* __restrict__ dst,
                const uint2* __restrict__ m1, const uint2* __restrict__ m2,
                const uint2* __restrict__ m3, float4* __restrict__ out,
                int* __restrict__ gcur, int last) {
    if (last && blockIdx.x == 0 && threadIdx.x < NBUCK) gcur[threadIdx.x] = 0;

    int row  = blockIdx.x * 8 + (threadIdx.x >> 5);
    int lane = threadIdx.x & 31;
    if (row >= N_NODES) return;

    int beg = __ldg(rowptr + row);
    int end = __ldg(rowptr + row + 1);

    int half = lane >> 4;
    int sub  = lane & 15;

    float a0 = 0.f, a1 = 0.f, a2 = 0.f, a3 = 0.f;
    int e = beg;

    for (; e + 16 <= end; e += 16) {
        int2 w[8];
        #pragma unroll
        for (int k = 0; k < 8; ++k) w[k] = __ldg(cv + e + 2 * k + half);
        uint2 g[8];
        #pragma unroll
        for (int k = 0; k < 8; ++k)
            g[k] = __ldcg(src + (size_t)w[k].x * 16 + sub);
        #pragma unroll
        for (int k = 0; k < 8; ++k) {
            float vv = __int_as_float(w[k].y);
            float2 p0 = __half22float2(*reinterpret_cast<__half2*>(&g[k].x));
            float2 p1 = __half22float2(*reinterpret_cast<__half2*>(&g[k].y));
            a0 = fmaf(vv, p0.x, a0); a1 = fmaf(vv, p0.y, a1);
            a2 = fmaf(vv, p1.x, a2); a3 = fmaf(vv, p1.y, a3);
        }
    }
    if (e + 8 <= end) {
        int2 w[4];
        #pragma unroll
        for (int k = 0; k < 4; ++k) w[k] = __ldg(cv + e + 2 * k + half);
        uint2 g[4];
        #pragma unroll
        for (int k = 0; k < 4; ++k)
            g[k] = __ldcg(src + (size_t)w[k].x * 16 + sub);
        #pragma unroll
        for (int k = 0; k < 4; ++k) {
            float vv = __int_as_float(w[k].y);
            float2 p0 = __half22float2(*reinterpret_cast<__half2*>(&g[k].x));
            float2 p1 = __half22float2(*reinterpret_cast<__half2*>(&g[k].y));
            a0 = fmaf(vv, p0.x, a0); a1 = fmaf(vv, p0.y, a1);
            a2 = fmaf(vv, p1.x, a2); a3 = fmaf(vv, p1.y, a3);
        }
        e += 8;
    }
    for (; e < end; e += 2) {
        int idx = e + half;
        int2 w = __ldg(cv + (idx < end ? idx : end - 1));
        float vv = (idx < end) ? __int_as_float(w.y) : 0.0f;
        uint2 g = __ldcg(src + (size_t)w.x * 16 + sub);
        float2 p0 = __half22float2(*reinterpret_cast<__half2*>(&g.x));
        float2 p1 = __half22float2(*reinterpret_cast<__half2*>(&g.y));
        a0 = fmaf(vv, p0.x, a0); a1 = fmaf(vv, p0.y, a1);
        a2 = fmaf(vv, p1.x, a2); a3 = fmaf(vv, p1.y, a3);
    }

    a0 += __shfl_xor_sync(0xFFFFFFFFu, a0, 16);
    a1 += __shfl_xor_sync(0xFFFFFFFFu, a1, 16);
    a2 += __shfl_xor_sync(0xFFFFFFFFu, a2, 16);
    a3 += __shfl_xor_sync(0xFFFFFFFFu, a3, 16);

    if (half == 0) {
        size_t o = (size_t)row * 16 + sub;
        if (!last) {
            __half2 h0 = __float22half2_rn(make_float2(a0, a1));
            __half2 h1 = __float22half2_rn(make_float2(a2, a3));
            uint2 r;
            r.x = *reinterpret_cast<uint32_t*>(&h0);
            r.y = *reinterpret_cast<uint32_t*>(&h1);
            dst[o] = r;
        } else {
            uint2 q1 = __ldg(m1 + o);
            uint2 q2 = __ldg(m2 + o);
            uint2 q3 = __ldg(m3 + o);
            float2 r1a = __half22float2(*reinterpret_cast<__half2*>(&q1.x));
            float2 r1b = __half22float2(*reinterpret_cast<__half2*>(&q1.y));
            float2 r2a = __half22float2(*reinterpret_cast<__half2*>(&q2.x));
            float2 r2b = __half22float2(*reinterpret_cast<__half2*>(&q2.y));
            float2 r3a = __half22float2(*reinterpret_cast<__half2*>(&q3.x));
            float2 r3b = __half22float2(*reinterpret_cast<__half2*>(&q3.y));
            float4 ov;
            ov.x = fmaf(4.f, r1a.x, fmaf(5.f, r2a.x, fmaf(3.f, r3a.x, a0)));
            ov.y = fmaf(4.f, r1a.y, fmaf(5.f, r2a.y, fmaf(3.f, r3a.y, a1)));
            ov.z = fmaf(4.f, r1b.x, fmaf(5.f, r2b.x, fmaf(3.f, r3b.x, a2)));
            ov.w = fmaf(4.f, r1b.y, fmaf(5.f, r2b.y, fmaf(3.f, r3b.y, a3)));
            out[o] = ov;
        }
    }
}

// ---------------------------------------------------------------------------
extern "C" void kernel_launch(void* const* d_in, const int* in_sizes, int n_in,
                              void* d_out, int out_size) {
    const float* x    = (const float*)d_in[0];
    const int*   rows = (const int*)  d_in[1];
    const int*   cols = (const int*)  d_in[2];
    const float* vals = (const float*)d_in[3];
    float*       out  = (float*)d_out;

    __half *h, *m1, *m2, *m3;
    int2   *cv, *stage;
    int    *gcur, *rowptr;
    cudaGetSymbolAddress((void**)&h,      g_h);
    cudaGetSymbolAddress((void**)&m1,     g_m1);
    cudaGetSymbolAddress((void**)&m2,     g_m2);
    cudaGetSymbolAddress((void**)&m3,     g_m3);
    cudaGetSymbolAddress((void**)&cv,     g_cv);
    cudaGetSymbolAddress((void**)&stage,  g_stage);
    cudaGetSymbolAddress((void**)&gcur,   g_gcur);
    cudaGetSymbolAddress((void**)&rowptr, g_rowptr);

    const int ROW_BLOCKS = (N_NODES + 7) / 8;   // 25000

    logmap_kernel<<<ROW_BLOCKS, 256>>>(x, (__half2*)h);
    phase1_bin_kernel<<<NNZ_E / TILE_E, 256>>>(rows, cols, vals, gcur, stage);
    phase2_csr_kernel<<<NBUCK, 1024>>>(gcur, stage, cv, rowptr);

    csr_spmm_kernel<<<ROW_BLOCKS, 256>>>(rowptr, cv, (const uint2*)h,  (uint2*)m1,
                                         nullptr, nullptr, nullptr, nullptr, gcur, 0);
    csr_spmm_kernel<<<ROW_BLOCKS, 256>>>(rowptr, cv, (const uint2*)m1, (uint2*)m2,
                                         nullptr, nullptr, nullptr, nullptr, gcur, 0);
    csr_spmm_kernel<<<ROW_BLOCKS, 256>>>(rowptr, cv, (const uint2*)m2, (uint2*)m3,
                                         nullptr, nullptr, nullptr, nullptr, gcur, 0);
    csr_spmm_kernel<<<ROW_BLOCKS, 256>>>(rowptr, cv, (const uint2*)m3, nullptr,
                                         (const uint2*)m1, (const uint2*)m2,
                                         (const uint2*)m3, (float4*)out, gcur, 1);
}